// round 9
// baseline (speedup 1.0000x reference)
#include <cuda_runtime.h>
#include <cuda_bf16.h>
#include <math.h>
#include <cstdint>

// ---------------- problem constants ----------------
#define BQ      3600
#define QD      256
#define TOT     24576
#define P1SZ    16384
#define OUTIN   16384
#define NSPLIT  32
#define NCTAS   148

// ---------------- scratch (device globals) ----------------
__device__ float g_params[(size_t)BQ * TOT];
__device__ float g_part[(size_t)NSPLIT * BQ * QD];
__device__ __nv_bfloat16 g_qf_hi[(size_t)BQ * QD];
__device__ __nv_bfloat16 g_qf_lo[(size_t)BQ * QD];
__device__ __nv_bfloat16 g_wgt_hi[(size_t)TOT * QD];     // W_gen^T [N,K]
__device__ __nv_bfloat16 g_wgt_lo[(size_t)TOT * QD];
__device__ __nv_bfloat16 g_wot_hi[(size_t)QD * OUTIN];   // W_out^T [N,K]
__device__ __nv_bfloat16 g_wot_lo[(size_t)QD * OUTIN];
__device__ __nv_bfloat16 g_out2_hi[(size_t)BQ * OUTIN];
__device__ __nv_bfloat16 g_out2_lo[(size_t)BQ * OUTIN];

// ---------------- PTX helpers ----------------
__device__ __forceinline__ uint32_t smem_u32(const void* p) {
    uint32_t a;
    asm("{ .reg .u64 t; cvta.to.shared.u64 t, %1; cvt.u32.u64 %0, t; }" : "=r"(a) : "l"(p));
    return a;
}
__device__ __forceinline__ void cp_async16(uint32_t dst, const void* src, uint32_t ssize) {
    asm volatile("cp.async.cg.shared.global [%0], [%1], 16, %2;"
                 :: "r"(dst), "l"(src), "r"(ssize) : "memory");
}
#define CP_COMMIT() asm volatile("cp.async.commit_group;" ::: "memory")
#define CP_WAIT1()  asm volatile("cp.async.wait_group 1;" ::: "memory")

__device__ __forceinline__ void ldsm4(uint32_t* r, uint32_t addr) {
    asm volatile("ldmatrix.sync.aligned.m8n8.x4.shared.b16 {%0,%1,%2,%3}, [%4];"
                 : "=r"(r[0]), "=r"(r[1]), "=r"(r[2]), "=r"(r[3]) : "r"(addr));
}
__device__ __forceinline__ void mma_bf16(float* c, const uint32_t* a, const uint32_t* b) {
    asm volatile(
        "mma.sync.aligned.m16n8k16.row.col.f32.bf16.bf16.f32 "
        "{%0,%1,%2,%3}, {%4,%5,%6,%7}, {%8,%9}, {%0,%1,%2,%3};"
        : "+f"(c[0]), "+f"(c[1]), "+f"(c[2]), "+f"(c[3])
        : "r"(a[0]), "r"(a[1]), "r"(a[2]), "r"(a[3]), "r"(b[0]), "r"(b[1]));
}

#define SWC(r, c) ((((c) + (r) + ((r) >> 2)) & 3))

// ---------------- misc helpers ----------------
__device__ __forceinline__ float gelu_exact(float x) {
    return 0.5f * x * (1.0f + erff(x * 0.70710678118654752f));
}
__device__ __forceinline__ void fma4(float4& a, float s, const float4& b) {
    a.x = fmaf(s, b.x, a.x); a.y = fmaf(s, b.y, a.y);
    a.z = fmaf(s, b.z, a.z); a.w = fmaf(s, b.w, a.w);
}
__device__ __forceinline__ void gelu4_acc(float4& v, float& s, float& q) {
    v.x = gelu_exact(v.x); v.y = gelu_exact(v.y);
    v.z = gelu_exact(v.z); v.w = gelu_exact(v.w);
    s += v.x + v.y + v.z + v.w;
    q += v.x * v.x + v.y * v.y + v.z * v.z + v.w * v.w;
}
__device__ __forceinline__ void blockReduce2(float& s, float& q) {
    __shared__ float rs[8], rq[8];
    #pragma unroll
    for (int o = 16; o > 0; o >>= 1) {
        s += __shfl_down_sync(0xffffffffu, s, o);
        q += __shfl_down_sync(0xffffffffu, q, o);
    }
    int w = threadIdx.x >> 5, l = threadIdx.x & 31;
    if (l == 0) { rs[w] = s; rq[w] = q; }
    __syncthreads();
    if (w == 0) {
        float ts = (l < 8) ? rs[l] : 0.f;
        float tq = (l < 8) ? rq[l] : 0.f;
        #pragma unroll
        for (int o = 4; o > 0; o >>= 1) {
            ts += __shfl_down_sync(0xffu, ts, o);
            tq += __shfl_down_sync(0xffu, tq, o);
        }
        if (l == 0) { rs[0] = ts; rq[0] = tq; }
    }
    __syncthreads();
    s = rs[0]; q = rq[0];
    __syncthreads();
}

// ---------------- prep kernels ----------------
__global__ void __launch_bounds__(256)
split_kernel(const float* __restrict__ src, __nv_bfloat16* __restrict__ dhi,
             __nv_bfloat16* __restrict__ dlo, int n)
{
    int i = blockIdx.x * 256 + threadIdx.x;
    if (i < n) {
        float x = src[i];
        __nv_bfloat16 h = __float2bfloat16(x);
        dhi[i] = h;
        dlo[i] = __float2bfloat16(x - __bfloat162float(h));
    }
}

__global__ void __launch_bounds__(256)
transpose_split_kernel(const float* __restrict__ src, __nv_bfloat16* __restrict__ dhi,
                       __nv_bfloat16* __restrict__ dlo, int R, int C)
{
    __shared__ float tile[32][33];
    int c0 = blockIdx.x * 32, r0 = blockIdx.y * 32;
    int tx = threadIdx.x & 31, ty = threadIdx.x >> 5;
    #pragma unroll
    for (int i = ty; i < 32; i += 8)
        tile[i][tx] = src[(size_t)(r0 + i) * C + c0 + tx];
    __syncthreads();
    #pragma unroll
    for (int i = ty; i < 32; i += 8) {
        float x = tile[tx][i];
        __nv_bfloat16 h = __float2bfloat16(x);
        size_t o = (size_t)(c0 + i) * R + r0 + tx;
        dhi[o] = h;
        dlo[o] = __float2bfloat16(x - __bfloat162float(h));
    }
}

// ---------------- persistent HMMA bf16x3 GEMM, CTA tile 128x256 ----------------
// 8 warps, warp tile 64x64 (2 x 4). A[M,K] hi/lo, B[N,K] hi/lo, K-major.
// Stage: A_hi 8K | A_lo 8K | B_hi 16K | B_lo 16K = 48KB; 3-stage ring = 144KB.
#define STAGE_BYTES 49152
#define GEMM_NSTAGE 3
#define SMEM_BYTES  (GEMM_NSTAGE * STAGE_BYTES)
#define MT 29               // ceil(3600/128)

__device__ __forceinline__ void load_stage(
    uint32_t sbase,
    const __nv_bfloat16* __restrict__ Ahi, const __nv_bfloat16* __restrict__ Alo,
    const __nv_bfloat16* __restrict__ Bhi, const __nv_bfloat16* __restrict__ Blo,
    int m_base, int n_base, int k0, int M, int K, int tid)
{
    // A: 128 rows x 4 chunks x 2 arrays = 1024 16B-chunks
    #pragma unroll
    for (int i = 0; i < 4; i++) {
        int idx = i * 256 + tid;
        int arr = idx >> 9;              // 0:Ahi 1:Alo
        int rc  = idx & 511;
        int row = rc >> 2;
        int c   = rc & 3;
        uint32_t so = sbase + arr * 8192 + row * 64 + SWC(row, c) * 16;
        int gm = m_base + row;
        int gr = (gm < M) ? gm : 0;
        uint32_t sz = (gm < M) ? 16 : 0;
        const __nv_bfloat16* src = (arr == 0 ? Ahi : Alo) + (size_t)gr * K + k0 + c * 8;
        cp_async16(so, src, sz);
    }
    // B: 256 rows x 4 chunks x 2 arrays = 2048 16B-chunks
    #pragma unroll
    for (int i = 0; i < 8; i++) {
        int idx = i * 256 + tid;
        int arr = idx >> 10;             // 0:Bhi 1:Blo
        int rc  = idx & 1023;
        int row = rc >> 2;
        int c   = rc & 3;
        uint32_t so = sbase + 16384 + arr * 16384 + row * 64 + SWC(row, c) * 16;
        const __nv_bfloat16* src = (arr == 0 ? Bhi : Blo) + (size_t)(n_base + row) * K + k0 + c * 8;
        cp_async16(so, src, 16);
    }
}

template<int NCH, int NT>
__global__ void __launch_bounds__(256, 1)
hmma_gemm_pers(const __nv_bfloat16* __restrict__ Ahi, const __nv_bfloat16* __restrict__ Alo,
               const __nv_bfloat16* __restrict__ Bhi, const __nv_bfloat16* __restrict__ Blo,
               const float* __restrict__ bias, float* __restrict__ C,
               int M, int K, int Kchunk, int ldc, size_t czstride, int total_tiles)
{
    extern __shared__ char smem_raw[];
    const uint32_t sbase = smem_u32(smem_raw);

    const int tid = threadIdx.x;
    const int wid = tid >> 5;
    const int lane = tid & 31;
    const int warp_m = wid & 1;      // 0..1  -> 64-row slab
    const int warp_n = wid >> 1;     // 0..3  -> 64-col slab
    const int G = gridDim.x;
    const int bid = blockIdx.x;

    int my_tiles = (bid < total_tiles) ? (total_tiles - bid + G - 1) / G : 0;
    const int my_chunks = my_tiles * NCH;

    auto tileof = [&](int L, int& mb, int& nb, int& z, int& c) {
        int tj = L / NCH; c = L - tj * NCH;
        int t = bid + tj * G;
        z = t / (MT * NT); int r = t - z * (MT * NT);
        int rm = r / NT;
        mb = rm * 128; nb = (r - rm * NT) * 256;
    };

    float acc[4][8][4];
    #pragma unroll
    for (int mi = 0; mi < 4; mi++)
        #pragma unroll
        for (int nj = 0; nj < 8; nj++)
            #pragma unroll
            for (int v = 0; v < 4; v++) acc[mi][nj][v] = 0.f;

    // prologue: prefetch chunks 0,1
    {
        int mb, nb, z, c;
        if (my_chunks > 0) {
            tileof(0, mb, nb, z, c);
            load_stage(sbase, Ahi, Alo, Bhi, Blo, mb, nb, z * Kchunk, M, K, tid);
        }
        CP_COMMIT();
        if (my_chunks > 1) {
            tileof(1, mb, nb, z, c);
            load_stage(sbase + STAGE_BYTES, Ahi, Alo, Bhi, Blo, mb, nb,
                       z * Kchunk + c * 32, M, K, tid);
        }
        CP_COMMIT();
    }

    for (int L = 0; L < my_chunks; L++) {
        CP_WAIT1();
        __syncthreads();

        if (L + 2 < my_chunks) {
            int mb, nb, z, c;
            tileof(L + 2, mb, nb, z, c);
            load_stage(sbase + (uint32_t)((L + 2) % GEMM_NSTAGE) * STAGE_BYTES,
                       Ahi, Alo, Bhi, Blo, mb, nb, z * Kchunk + c * 32, M, K, tid);
        }
        CP_COMMIT();

        int mb, nb, z, cc;
        tileof(L, mb, nb, z, cc);

        const uint32_t st = sbase + (uint32_t)(L % GEMM_NSTAGE) * STAGE_BYTES;
        const uint32_t sA_hi = st, sA_lo = st + 8192;
        const uint32_t sB_hi = st + 16384, sB_lo = st + 32768;

        #pragma unroll
        for (int kk = 0; kk < 2; kk++) {
            uint32_t ah[4][4], al[4][4], bh[8][2], bl[8][2];

            const int alr = lane & 15;
            const int alc = kk * 2 + (lane >> 4);
            #pragma unroll
            for (int mi = 0; mi < 4; mi++) {
                int row = warp_m * 64 + mi * 16 + alr;
                uint32_t off = (uint32_t)(row * 64 + SWC(row, alc) * 16);
                ldsm4(ah[mi], sA_hi + off);
                ldsm4(al[mi], sA_lo + off);
            }
            const int blr = (lane & 7) + ((lane >> 4) << 3);
            const int blc = kk * 2 + ((lane >> 3) & 1);
            #pragma unroll
            for (int p = 0; p < 4; p++) {
                int row = warp_n * 64 + p * 16 + blr;
                uint32_t off = (uint32_t)(row * 64 + SWC(row, blc) * 16);
                uint32_t t[4];
                ldsm4(t, sB_hi + off);
                bh[p * 2][0] = t[0]; bh[p * 2][1] = t[1];
                bh[p * 2 + 1][0] = t[2]; bh[p * 2 + 1][1] = t[3];
                ldsm4(t, sB_lo + off);
                bl[p * 2][0] = t[0]; bl[p * 2][1] = t[1];
                bl[p * 2 + 1][0] = t[2]; bl[p * 2 + 1][1] = t[3];
            }

            #pragma unroll
            for (int mi = 0; mi < 4; mi++)
                #pragma unroll
                for (int nj = 0; nj < 8; nj++)
                    mma_bf16(acc[mi][nj], ah[mi], bh[nj]);
            #pragma unroll
            for (int mi = 0; mi < 4; mi++)
                #pragma unroll
                for (int nj = 0; nj < 8; nj++)
                    mma_bf16(acc[mi][nj], ah[mi], bl[nj]);
            #pragma unroll
            for (int mi = 0; mi < 4; mi++)
                #pragma unroll
                for (int nj = 0; nj < 8; nj++)
                    mma_bf16(acc[mi][nj], al[mi], bh[nj]);
        }

        // tile finished -> epilogue (overlaps in-flight cp.async of next tile)
        if (cc == NCH - 1) {
            float* Cz = C + (size_t)z * czstride;
            const int er = lane >> 2;
            const int ec = (lane & 3) * 2;
            #pragma unroll
            for (int mi = 0; mi < 4; mi++) {
                int gm0 = mb + warp_m * 64 + mi * 16 + er;
                #pragma unroll
                for (int nj = 0; nj < 8; nj++) {
                    int col = nb + warp_n * 64 + nj * 8 + ec;
                    float bx = 0.f, by = 0.f;
                    if (bias) {
                        float2 bv = *reinterpret_cast<const float2*>(bias + col);
                        bx = bv.x; by = bv.y;
                    }
                    if (gm0 < M) {
                        float2 v = make_float2(acc[mi][nj][0] + bx, acc[mi][nj][1] + by);
                        *reinterpret_cast<float2*>(Cz + (size_t)gm0 * ldc + col) = v;
                    }
                    if (gm0 + 8 < M) {
                        float2 v = make_float2(acc[mi][nj][2] + bx, acc[mi][nj][3] + by);
                        *reinterpret_cast<float2*>(Cz + (size_t)(gm0 + 8) * ldc + col) = v;
                    }
                    #pragma unroll
                    for (int v = 0; v < 4; v++) acc[mi][nj][v] = 0.f;
                }
            }
        }
    }
}

// ---------------- fused mixer (float4-vectorized) ----------------
__global__ void __launch_bounds__(256)
mixer_kernel(const float* __restrict__ sampled)
{
    const int bq = blockIdx.x;
    const int h  = blockIdx.y;
    const float* par = g_params + (size_t)bq * TOT;

    __shared__ float4 s4[512];    // sampled  [p=32][c=64]
    __shared__ float4 p14[1024];  // p1       [c=64][d=64]
    __shared__ float4 p24[512];   // p2       [e=64][p=32]
    __shared__ float4 o14[512];   // o1       [p=32][d=64]

    const int t  = threadIdx.x;
    const int dq = t & 15;
    const int g  = t >> 4;

    {
        const float4* sp = reinterpret_cast<const float4*>(
            sampled + ((size_t)bq * 4 + h) * 2048);
        for (int i = t; i < 512; i += 256) s4[i] = sp[i];
        const float4* p1p = reinterpret_cast<const float4*>(par + h * 4096);
        for (int i = t; i < 1024; i += 256) p14[i] = p1p[i];
        const float4* p2p = reinterpret_cast<const float4*>(par + P1SZ + h * 2048);
        for (int i = t; i < 512; i += 256) p24[i] = p2p[i];
    }
    __syncthreads();

    float4 a0 = make_float4(0.f, 0.f, 0.f, 0.f);
    float4 a1 = make_float4(0.f, 0.f, 0.f, 0.f);
    #pragma unroll
    for (int cb = 0; cb < 16; cb++) {
        float4 s0 = s4[g * 16 + cb];
        float4 s1 = s4[(g + 16) * 16 + cb];
        float4 pv;
        pv = p14[(cb * 4 + 0) * 16 + dq]; fma4(a0, s0.x, pv); fma4(a1, s1.x, pv);
        pv = p14[(cb * 4 + 1) * 16 + dq]; fma4(a0, s0.y, pv); fma4(a1, s1.y, pv);
        pv = p14[(cb * 4 + 2) * 16 + dq]; fma4(a0, s0.z, pv); fma4(a1, s1.z, pv);
        pv = p14[(cb * 4 + 3) * 16 + dq]; fma4(a0, s0.w, pv); fma4(a1, s1.w, pv);
    }
    float s = 0.f, q = 0.f;
    gelu4_acc(a0, s, q);
    gelu4_acc(a1, s, q);
    blockReduce2(s, q);
    {
        float mean = s * (1.f / 2048.f);
        float var  = q * (1.f / 2048.f) - mean * mean;
        float rsig = rsqrtf(var + 1e-5f);
        float4 n0, n1;
        n0.x = (a0.x - mean) * rsig; n0.y = (a0.y - mean) * rsig;
        n0.z = (a0.z - mean) * rsig; n0.w = (a0.w - mean) * rsig;
        n1.x = (a1.x - mean) * rsig; n1.y = (a1.y - mean) * rsig;
        n1.z = (a1.z - mean) * rsig; n1.w = (a1.w - mean) * rsig;
        o14[g * 16 + dq] = n0;
        o14[(g + 16) * 16 + dq] = n1;
    }
    __syncthreads();

    float4 c0 = make_float4(0.f, 0.f, 0.f, 0.f);
    float4 c1 = c0, c2 = c0, c3 = c0;
    #pragma unroll
    for (int pb = 0; pb < 8; pb++) {
        float4 w0 = p24[g * 8 + pb];
        float4 w1 = p24[(g + 16) * 8 + pb];
        float4 w2 = p24[(g + 32) * 8 + pb];
        float4 w3 = p24[(g + 48) * 8 + pb];
        float4 ov;
        ov = o14[(pb * 4 + 0) * 16 + dq];
        fma4(c0, w0.x, ov); fma4(c1, w1.x, ov); fma4(c2, w2.x, ov); fma4(c3, w3.x, ov);
        ov = o14[(pb * 4 + 1) * 16 + dq];
        fma4(c0, w0.y, ov); fma4(c1, w1.y, ov); fma4(c2, w2.y, ov); fma4(c3, w3.y, ov);
        ov = o14[(pb * 4 + 2) * 16 + dq];
        fma4(c0, w0.z, ov); fma4(c1, w1.z, ov); fma4(c2, w2.z, ov); fma4(c3, w3.z, ov);
        ov = o14[(pb * 4 + 3) * 16 + dq];
        fma4(c0, w0.w, ov); fma4(c1, w1.w, ov); fma4(c2, w2.w, ov); fma4(c3, w3.w, ov);
    }
    s = 0.f; q = 0.f;
    gelu4_acc(c0, s, q);
    gelu4_acc(c1, s, q);
    gelu4_acc(c2, s, q);
    gelu4_acc(c3, s, q);
    blockReduce2(s, q);
    float mean = s * (1.f / 4096.f);
    float var  = q * (1.f / 4096.f) - mean * mean;
    float rsig = rsqrtf(var + 1e-5f);

    __nv_bfloat16* ohi = g_out2_hi + (size_t)bq * OUTIN + h * 4096;
    __nv_bfloat16* olo = g_out2_lo + (size_t)bq * OUTIN + h * 4096;
    float4 cc[4] = {c0, c1, c2, c3};
    #pragma unroll
    for (int i = 0; i < 4; i++) {
        int e = g + 16 * i;
        float vx[4] = {cc[i].x, cc[i].y, cc[i].z, cc[i].w};
        ushort4 hv, lv;
        unsigned short* hp = &hv.x;
        unsigned short* lp = &lv.x;
        #pragma unroll
        for (int j = 0; j < 4; j++) {
            float gg = (vx[j] - mean) * rsig;
            __nv_bfloat16 hb = __float2bfloat16(gg);
            __nv_bfloat16 lb = __float2bfloat16(gg - __bfloat162float(hb));
            hp[j] = *reinterpret_cast<unsigned short*>(&hb);
            lp[j] = *reinterpret_cast<unsigned short*>(&lb);
        }
        *reinterpret_cast<ushort4*>(ohi + e * 64 + dq * 4) = hv;
        *reinterpret_cast<ushort4*>(olo + e * 64 + dq * 4) = lv;
    }
}

// ---------------- split-K reduce + bias + final affine LN ----------------
__global__ void __launch_bounds__(256)
reduce_ln_kernel(const float* __restrict__ b_out,
                 const float* __restrict__ ln_w, const float* __restrict__ ln_b,
                 float* __restrict__ out)
{
    const int r = blockIdx.x;
    const int t = threadIdx.x;
    float x = b_out[t];
    #pragma unroll
    for (int z = 0; z < NSPLIT; z++)
        x += g_part[(size_t)z * BQ * QD + (size_t)r * QD + t];
    float s = x, q = x * x;
    blockReduce2(s, q);
    float mean = s * (1.f / 256.f);
    float var  = q * (1.f / 256.f) - mean * mean;
    float rsig = rsqrtf(var + 1e-5f);
    out[(size_t)r * QD + t] = (x - mean) * rsig * ln_w[t] + ln_b[t];
}

// ---------------- launch ----------------
extern "C" void kernel_launch(void* const* d_in, const int* in_sizes, int n_in,
                              void* d_out, int out_size)
{
    const float* qf = (const float*)d_in[0];
    const float* sf = (const float*)d_in[1];
    const float* Wg = (const float*)d_in[2];
    const float* bg = (const float*)d_in[3];
    const float* Wo = (const float*)d_in[4];
    const float* bo = (const float*)d_in[5];
    const float* lw = (const float*)d_in[6];
    const float* lb = (const float*)d_in[7];
    float* out = (float*)d_out;

    cudaFuncSetAttribute(hmma_gemm_pers<8, 96>,
                         cudaFuncAttributeMaxDynamicSharedMemorySize, SMEM_BYTES);
    cudaFuncSetAttribute(hmma_gemm_pers<16, 1>,
                         cudaFuncAttributeMaxDynamicSharedMemorySize, SMEM_BYTES);

    float *params_p, *part_p;
    __nv_bfloat16 *qfh, *qfl, *wgh, *wgl, *woh, *wol, *o2h, *o2l;
    cudaGetSymbolAddress((void**)&params_p, g_params);
    cudaGetSymbolAddress((void**)&part_p, g_part);
    cudaGetSymbolAddress((void**)&qfh, g_qf_hi);
    cudaGetSymbolAddress((void**)&qfl, g_qf_lo);
    cudaGetSymbolAddress((void**)&wgh, g_wgt_hi);
    cudaGetSymbolAddress((void**)&wgl, g_wgt_lo);
    cudaGetSymbolAddress((void**)&woh, g_wot_hi);
    cudaGetSymbolAddress((void**)&wol, g_wot_lo);
    cudaGetSymbolAddress((void**)&o2h, g_out2_hi);
    cudaGetSymbolAddress((void**)&o2l, g_out2_lo);

    // prep
    split_kernel<<<(BQ * QD + 255) / 256, 256>>>(qf, qfh, qfl, BQ * QD);
    transpose_split_kernel<<<dim3(TOT / 32, QD / 32), 256>>>(Wg, wgh, wgl, QD, TOT);
    transpose_split_kernel<<<dim3(QD / 32, OUTIN / 32), 256>>>(Wo, woh, wol, OUTIN, QD);

    // GEMM1: params = qf @ W_gen + b_gen   (3600 x 24576 x 256)
    // tiles = 29 * 96 = 2784, nch = 8 (K=256)
    hmma_gemm_pers<8, 96><<<NCTAS, 256, SMEM_BYTES>>>(
        qfh, qfl, wgh, wgl, bg, params_p, BQ, QD, QD, TOT, 0, MT * 96);

    // fused mixers
    mixer_kernel<<<dim3(BQ, 4), 256>>>(sf);

    // GEMM3 split-K=32: out2 @ W_out partials   (3600 x 256 x 16384)
    // Kchunk = 512, nch = 16, NT = 1, tiles = 32 * 29 = 928
    hmma_gemm_pers<16, 1><<<NCTAS, 256, SMEM_BYTES>>>(
        o2h, o2l, woh, wol, nullptr, part_p, BQ, OUTIN, OUTIN / NSPLIT,
        QD, (size_t)BQ * QD, NSPLIT * MT);

    // reduce + final LN
    reduce_ln_kernel<<<BQ, 256>>>(bo, lw, lb, out);
}

// round 11
// speedup vs baseline: 1.1427x; 1.1427x over previous
#include <cuda_runtime.h>
#include <cuda_bf16.h>
#include <math.h>
#include <cstdint>

// ---------------- problem constants ----------------
#define BQ      3600
#define QD      256
#define TOT     24576
#define P1SZ    16384
#define OUTIN   16384
#define NSPLIT  16

// ---------------- scratch (device globals) ----------------
__device__ float g_params[(size_t)BQ * TOT];
__device__ float g_part[(size_t)NSPLIT * BQ * QD];
__device__ __nv_bfloat16 g_qf_hi[(size_t)BQ * QD];
__device__ __nv_bfloat16 g_qf_lo[(size_t)BQ * QD];
__device__ __nv_bfloat16 g_wgt_hi[(size_t)TOT * QD];     // W_gen^T [N,K]
__device__ __nv_bfloat16 g_wgt_lo[(size_t)TOT * QD];
__device__ __nv_bfloat16 g_wot_hi[(size_t)QD * OUTIN];   // W_out^T [N,K]
__device__ __nv_bfloat16 g_wot_lo[(size_t)QD * OUTIN];
__device__ __nv_bfloat16 g_out2_hi[(size_t)BQ * OUTIN];
__device__ __nv_bfloat16 g_out2_lo[(size_t)BQ * OUTIN];

// ---------------- PTX helpers ----------------
__device__ __forceinline__ uint32_t smem_u32(const void* p) {
    uint32_t a;
    asm("{ .reg .u64 t; cvta.to.shared.u64 t, %1; cvt.u32.u64 %0, t; }" : "=r"(a) : "l"(p));
    return a;
}
__device__ __forceinline__ void cp_async16(uint32_t dst, const void* src, uint32_t ssize) {
    asm volatile("cp.async.cg.shared.global [%0], [%1], 16, %2;"
                 :: "r"(dst), "l"(src), "r"(ssize) : "memory");
}
#define CP_COMMIT() asm volatile("cp.async.commit_group;" ::: "memory")
#define CP_WAIT(N)  asm volatile("cp.async.wait_group %0;" :: "n"(N) : "memory")

__device__ __forceinline__ void ldsm4(uint32_t* r, uint32_t addr) {
    asm volatile("ldmatrix.sync.aligned.m8n8.x4.shared.b16 {%0,%1,%2,%3}, [%4];"
                 : "=r"(r[0]), "=r"(r[1]), "=r"(r[2]), "=r"(r[3]) : "r"(addr));
}
__device__ __forceinline__ void ldsm4t(uint32_t* r, uint32_t addr) {
    asm volatile("ldmatrix.sync.aligned.m8n8.x4.trans.shared.b16 {%0,%1,%2,%3}, [%4];"
                 : "=r"(r[0]), "=r"(r[1]), "=r"(r[2]), "=r"(r[3]) : "r"(addr));
}
__device__ __forceinline__ void mma_bf16(float* c, const uint32_t* a, const uint32_t* b) {
    asm volatile(
        "mma.sync.aligned.m16n8k16.row.col.f32.bf16.bf16.f32 "
        "{%0,%1,%2,%3}, {%4,%5,%6,%7}, {%8,%9}, {%0,%1,%2,%3};"
        : "+f"(c[0]), "+f"(c[1]), "+f"(c[2]), "+f"(c[3])
        : "r"(a[0]), "r"(a[1]), "r"(a[2]), "r"(a[3]), "r"(b[0]), "r"(b[1]));
}

#define SWC(r, c)  ((((c) + (r) + ((r) >> 2)) & 3))   // 64B rows (4 chunks)
#define SW8(r, c)  ((((c) + (r)) & 7))                // 128B rows (8 chunks)

// ---------------- misc helpers ----------------
__device__ __forceinline__ float gelu_exact(float x) {
    return 0.5f * x * (1.0f + erff(x * 0.70710678118654752f));
}
__device__ __forceinline__ uint32_t packbf(__nv_bfloat16 a, __nv_bfloat16 b) {
    uint16_t ua = *(uint16_t*)&a, ub = *(uint16_t*)&b;
    return (uint32_t)ua | ((uint32_t)ub << 16);
}
__device__ __forceinline__ void split4(float4 v, uint2& hi, uint2& lo) {
    __nv_bfloat16 h0 = __float2bfloat16(v.x), h1 = __float2bfloat16(v.y);
    __nv_bfloat16 h2 = __float2bfloat16(v.z), h3 = __float2bfloat16(v.w);
    __nv_bfloat16 l0 = __float2bfloat16(v.x - __bfloat162float(h0));
    __nv_bfloat16 l1 = __float2bfloat16(v.y - __bfloat162float(h1));
    __nv_bfloat16 l2 = __float2bfloat16(v.z - __bfloat162float(h2));
    __nv_bfloat16 l3 = __float2bfloat16(v.w - __bfloat162float(h3));
    hi.x = packbf(h0, h1); hi.y = packbf(h2, h3);
    lo.x = packbf(l0, l1); lo.y = packbf(l2, l3);
}
__device__ __forceinline__ void blockReduce2(float& s, float& q) {
    __shared__ float rs[8], rq[8];
    #pragma unroll
    for (int o = 16; o > 0; o >>= 1) {
        s += __shfl_down_sync(0xffffffffu, s, o);
        q += __shfl_down_sync(0xffffffffu, q, o);
    }
    int w = threadIdx.x >> 5, l = threadIdx.x & 31;
    if (l == 0) { rs[w] = s; rq[w] = q; }
    __syncthreads();
    if (w == 0) {
        float ts = (l < 8) ? rs[l] : 0.f;
        float tq = (l < 8) ? rq[l] : 0.f;
        #pragma unroll
        for (int o = 4; o > 0; o >>= 1) {
            ts += __shfl_down_sync(0xffu, ts, o);
            tq += __shfl_down_sync(0xffu, tq, o);
        }
        if (l == 0) { rs[0] = ts; rq[0] = tq; }
    }
    __syncthreads();
    s = rs[0]; q = rq[0];
    __syncthreads();
}

// ---------------- prep kernels ----------------
__global__ void __launch_bounds__(256)
split_kernel(const float* __restrict__ src, __nv_bfloat16* __restrict__ dhi,
             __nv_bfloat16* __restrict__ dlo, int n)
{
    int i = blockIdx.x * 256 + threadIdx.x;
    if (i < n) {
        float x = src[i];
        __nv_bfloat16 h = __float2bfloat16(x);
        dhi[i] = h;
        dlo[i] = __float2bfloat16(x - __bfloat162float(h));
    }
}

__global__ void __launch_bounds__(256)
transpose_split_kernel(const float* __restrict__ src, __nv_bfloat16* __restrict__ dhi,
                       __nv_bfloat16* __restrict__ dlo, int R, int C)
{
    __shared__ float tile[32][33];
    int c0 = blockIdx.x * 32, r0 = blockIdx.y * 32;
    int tx = threadIdx.x & 31, ty = threadIdx.x >> 5;
    #pragma unroll
    for (int i = ty; i < 32; i += 8)
        tile[i][tx] = src[(size_t)(r0 + i) * C + c0 + tx];
    __syncthreads();
    #pragma unroll
    for (int i = ty; i < 32; i += 8) {
        float x = tile[tx][i];
        __nv_bfloat16 h = __float2bfloat16(x);
        size_t o = (size_t)(c0 + i) * R + r0 + tx;
        dhi[o] = h;
        dlo[o] = __float2bfloat16(x - __bfloat162float(h));
    }
}

// ---------------- HMMA bf16x3 GEMM (R6 config: 128x128, 3-stage, 2 CTA/SM) ----------------
#define STAGE_BYTES 32768
#define GEMM_NSTAGE 3
#define SMEM_BYTES  (GEMM_NSTAGE * STAGE_BYTES)

__device__ __forceinline__ void load_stage(
    uint32_t sbase,
    const __nv_bfloat16* __restrict__ Ahi, const __nv_bfloat16* __restrict__ Alo,
    const __nv_bfloat16* __restrict__ Bhi, const __nv_bfloat16* __restrict__ Blo,
    int m_base, int n_base, int k0, int M, int K, int tid)
{
    #pragma unroll
    for (int i = 0; i < 8; i++) {
        int idx = i * 256 + tid;
        int arr = idx >> 9;          // 0:Ahi 1:Alo 2:Bhi 3:Blo
        int rc  = idx & 511;
        int row = rc >> 2;
        int c   = rc & 3;
        uint32_t so = sbase + arr * 8192 + row * 64 + SWC(row, c) * 16;
        const __nv_bfloat16* src;
        uint32_t sz = 16;
        if (arr < 2) {
            int gm = m_base + row;
            int gr = (gm < M) ? gm : 0;
            if (gm >= M) sz = 0;
            src = (arr == 0 ? Ahi : Alo) + (size_t)gr * K + k0 + c * 8;
        } else {
            src = (arr == 2 ? Bhi : Blo) + (size_t)(n_base + row) * K + k0 + c * 8;
        }
        cp_async16(so, src, sz);
    }
}

__global__ void __launch_bounds__(256, 2)
hmma_gemm(const __nv_bfloat16* __restrict__ Ahi, const __nv_bfloat16* __restrict__ Alo,
          const __nv_bfloat16* __restrict__ Bhi, const __nv_bfloat16* __restrict__ Blo,
          const float* __restrict__ bias, float* __restrict__ C,
          int M, int K, int nch, int ldc, size_t czstride)
{
    extern __shared__ char smem_raw[];
    const uint32_t sbase = smem_u32(smem_raw);

    const int tid = threadIdx.x;
    const int wid = tid >> 5;
    const int lane = tid & 31;
    const int warp_m = wid & 1;
    const int warp_n = wid >> 1;
    const int m_base = blockIdx.y * 128;
    const int n_base = blockIdx.x * 128;
    const int kbeg = blockIdx.z * nch * 32;
    C += (size_t)blockIdx.z * czstride;

    float acc[4][4][4];
    #pragma unroll
    for (int mi = 0; mi < 4; mi++)
        #pragma unroll
        for (int nj = 0; nj < 4; nj++)
            #pragma unroll
            for (int v = 0; v < 4; v++) acc[mi][nj][v] = 0.f;

    load_stage(sbase, Ahi, Alo, Bhi, Blo, m_base, n_base, kbeg, M, K, tid);
    CP_COMMIT();
    if (nch > 1)
        load_stage(sbase + STAGE_BYTES, Ahi, Alo, Bhi, Blo,
                   m_base, n_base, kbeg + 32, M, K, tid);
    CP_COMMIT();

    for (int ch = 0; ch < nch; ch++) {
        __syncthreads();
        if (ch + 2 < nch)
            load_stage(sbase + (uint32_t)((ch + 2) % GEMM_NSTAGE) * STAGE_BYTES,
                       Ahi, Alo, Bhi, Blo, m_base, n_base,
                       kbeg + (ch + 2) * 32, M, K, tid);
        CP_COMMIT();
        CP_WAIT(2);
        __syncthreads();

        const uint32_t st = sbase + (uint32_t)(ch % GEMM_NSTAGE) * STAGE_BYTES;
        const uint32_t sA_hi = st, sA_lo = st + 8192;
        const uint32_t sB_hi = st + 16384, sB_lo = st + 24576;

        #pragma unroll
        for (int kk = 0; kk < 2; kk++) {
            uint32_t ah[4][4], al[4][4], bh[4][2], bl[4][2];

            const int alr = lane & 15;
            const int alc = kk * 2 + (lane >> 4);
            #pragma unroll
            for (int mi = 0; mi < 4; mi++) {
                int row = warp_m * 64 + mi * 16 + alr;
                uint32_t off = (uint32_t)(row * 64 + SWC(row, alc) * 16);
                ldsm4(ah[mi], sA_hi + off);
                ldsm4(al[mi], sA_lo + off);
            }
            const int blr = (lane & 7) + ((lane >> 4) << 3);
            const int blc = kk * 2 + ((lane >> 3) & 1);
            #pragma unroll
            for (int p = 0; p < 2; p++) {
                int row = warp_n * 32 + p * 16 + blr;
                uint32_t off = (uint32_t)(row * 64 + SWC(row, blc) * 16);
                uint32_t t[4];
                ldsm4(t, sB_hi + off);
                bh[p * 2][0] = t[0]; bh[p * 2][1] = t[1];
                bh[p * 2 + 1][0] = t[2]; bh[p * 2 + 1][1] = t[3];
                ldsm4(t, sB_lo + off);
                bl[p * 2][0] = t[0]; bl[p * 2][1] = t[1];
                bl[p * 2 + 1][0] = t[2]; bl[p * 2 + 1][1] = t[3];
            }

            #pragma unroll
            for (int mi = 0; mi < 4; mi++)
                #pragma unroll
                for (int nj = 0; nj < 4; nj++)
                    mma_bf16(acc[mi][nj], ah[mi], bh[nj]);
            #pragma unroll
            for (int mi = 0; mi < 4; mi++)
                #pragma unroll
                for (int nj = 0; nj < 4; nj++)
                    mma_bf16(acc[mi][nj], ah[mi], bl[nj]);
            #pragma unroll
            for (int mi = 0; mi < 4; mi++)
                #pragma unroll
                for (int nj = 0; nj < 4; nj++)
                    mma_bf16(acc[mi][nj], al[mi], bh[nj]);
        }
    }

    const int er = lane >> 2;
    const int ec = (lane & 3) * 2;
    float2 bv[4];
    if (bias) {
        #pragma unroll
        for (int nj = 0; nj < 4; nj++) {
            int col = n_base + warp_n * 32 + nj * 8 + ec;
            bv[nj] = *reinterpret_cast<const float2*>(bias + col);
        }
    } else {
        #pragma unroll
        for (int nj = 0; nj < 4; nj++) bv[nj] = make_float2(0.f, 0.f);
    }
    #pragma unroll
    for (int mi = 0; mi < 4; mi++) {
        int gm0 = m_base + warp_m * 64 + mi * 16 + er;
        #pragma unroll
        for (int nj = 0; nj < 4; nj++) {
            int col = n_base + warp_n * 32 + nj * 8 + ec;
            if (gm0 < M) {
                float2 v = make_float2(acc[mi][nj][0] + bv[nj].x,
                                       acc[mi][nj][1] + bv[nj].y);
                *reinterpret_cast<float2*>(C + (size_t)gm0 * ldc + col) = v;
            }
            if (gm0 + 8 < M) {
                float2 v = make_float2(acc[mi][nj][2] + bv[nj].x,
                                       acc[mi][nj][3] + bv[nj].y);
                *reinterpret_cast<float2*>(C + (size_t)(gm0 + 8) * ldc + col) = v;
            }
        }
    }
}

// ---------------- HMMA mixer ----------------
// per (bq,h): out1[32p x 64d] = s[32 x 64c] @ p1[64c x 64d]; gelu+LN2d;
//             out2[64e x 64d] = p2[64 x 32p] @ out1[32p x 64d]; gelu+LN2d.
// bf16 hi/lo (3-pass). A via ldsm; B via ldsm.trans ([k][n] n-contiguous storage).
#define OFF_SHI  0        // s_hi  [32][64]  4KB, 128B rows, SW8
#define OFF_SLO  4096
#define OFF_P1H  8192     // p1_hi [64][64]  8KB, 128B rows, SW8 (reused as out staging)
#define OFF_P1L  16384
#define OFF_P2H  24576    // p2_hi [64][32]  4KB, 64B rows, SWC
#define OFF_P2L  28672
#define OFF_O1H  32768    // o1_hi [32][64]  4KB, 128B rows, SW8
#define OFF_O1L  36864
#define MIX_SMEM 40960

__global__ void __launch_bounds__(256)
mixer_hmma(const float* __restrict__ sampled)
{
    const int bq = blockIdx.x, h = blockIdx.y;
    __shared__ __align__(16) char sm[MIX_SMEM];
    const uint32_t sb = smem_u32(sm);
    const int t = threadIdx.x, wid = t >> 5, lane = t & 31;

    // ---- load + split inputs ----
    {
        const float4* sp = (const float4*)(sampled + ((size_t)bq * 4 + h) * 2048);
        const float* par = g_params + (size_t)bq * TOT;
        const float4* p1p = (const float4*)(par + h * 4096);
        const float4* p2p = (const float4*)(par + P1SZ + h * 2048);

        #pragma unroll
        for (int j = 0; j < 2; j++) {           // sampled: 512 float4, 16/row
            int i4 = t + j * 256;
            float4 v = sp[i4];
            int row = i4 >> 4, col = (i4 & 15) * 4;
            uint32_t off = row * 128 + (SW8(row, col >> 3) << 4) + ((col & 7) << 1);
            uint2 hi, lo; split4(v, hi, lo);
            *(uint2*)(sm + OFF_SHI + off) = hi;
            *(uint2*)(sm + OFF_SLO + off) = lo;
        }
        #pragma unroll
        for (int j = 0; j < 4; j++) {           // p1: 1024 float4, 16/row
            int i4 = t + j * 256;
            float4 v = p1p[i4];
            int row = i4 >> 4, col = (i4 & 15) * 4;
            uint32_t off = row * 128 + (SW8(row, col >> 3) << 4) + ((col & 7) << 1);
            uint2 hi, lo; split4(v, hi, lo);
            *(uint2*)(sm + OFF_P1H + off) = hi;
            *(uint2*)(sm + OFF_P1L + off) = lo;
        }
        #pragma unroll
        for (int j = 0; j < 2; j++) {           // p2: 512 float4, 8/row (64B rows)
            int i4 = t + j * 256;
            float4 v = p2p[i4];
            int row = i4 >> 3, col = (i4 & 7) * 4;
            uint32_t off = row * 64 + (SWC(row, col >> 3) << 4) + ((col & 7) << 1);
            uint2 hi, lo; split4(v, hi, lo);
            *(uint2*)(sm + OFF_P2H + off) = hi;
            *(uint2*)(sm + OFF_P2L + off) = lo;
        }
    }
    __syncthreads();

    // ---- GEMM-A: out1 = s @ p1 ----  warp: m16 (wm) x n16 (wn)
    const int wm = wid & 1, wn = wid >> 1;
    float accA[2][4];
    #pragma unroll
    for (int nj = 0; nj < 2; nj++)
        #pragma unroll
        for (int v = 0; v < 4; v++) accA[nj][v] = 0.f;

    #pragma unroll
    for (int ks = 0; ks < 4; ks++) {
        uint32_t ah[4], al[4];
        {
            int ar = wm * 16 + (lane & 15);
            int ac = ks * 2 + (lane >> 4);
            uint32_t off = ar * 128 + (SW8(ar, ac) << 4);
            ldsm4(ah, sb + OFF_SHI + off);
            ldsm4(al, sb + OFF_SLO + off);
        }
        uint32_t bh[2][2], bl[2][2];
        {
            int grp = lane >> 3;
            int br = ks * 16 + ((grp & 1) << 3) + (lane & 7);
            int bc = wn * 2 + (grp >> 1);
            uint32_t off = br * 128 + (SW8(br, bc) << 4);
            uint32_t tb[4];
            ldsm4t(tb, sb + OFF_P1H + off);
            bh[0][0] = tb[0]; bh[0][1] = tb[1]; bh[1][0] = tb[2]; bh[1][1] = tb[3];
            ldsm4t(tb, sb + OFF_P1L + off);
            bl[0][0] = tb[0]; bl[0][1] = tb[1]; bl[1][0] = tb[2]; bl[1][1] = tb[3];
        }
        #pragma unroll
        for (int nj = 0; nj < 2; nj++) {
            mma_bf16(accA[nj], ah, bh[nj]);
            mma_bf16(accA[nj], ah, bl[nj]);
            mma_bf16(accA[nj], al, bh[nj]);
        }
    }

    // gelu + LN2d over 32x64
    float s = 0.f, q = 0.f;
    #pragma unroll
    for (int nj = 0; nj < 2; nj++)
        #pragma unroll
        for (int v = 0; v < 4; v++) {
            float g = gelu_exact(accA[nj][v]);
            accA[nj][v] = g; s += g; q += g * g;
        }
    blockReduce2(s, q);
    {
        float mean = s * (1.f / 2048.f);
        float var  = q * (1.f / 2048.f) - mean * mean;
        float rsig = rsqrtf(var + 1e-5f);
        #pragma unroll
        for (int nj = 0; nj < 2; nj++)
            #pragma unroll
            for (int half = 0; half < 2; half++) {
                int p = wm * 16 + (lane >> 2) + half * 8;
                int d0 = wn * 16 + nj * 8 + ((lane & 3) << 1);
                float x0 = (accA[nj][half * 2 + 0] - mean) * rsig;
                float x1 = (accA[nj][half * 2 + 1] - mean) * rsig;
                __nv_bfloat16 h0 = __float2bfloat16(x0), h1 = __float2bfloat16(x1);
                __nv_bfloat16 l0 = __float2bfloat16(x0 - __bfloat162float(h0));
                __nv_bfloat16 l1 = __float2bfloat16(x1 - __bfloat162float(h1));
                uint32_t off = p * 128 + (SW8(p, d0 >> 3) << 4) + ((d0 & 7) << 1);
                *(uint32_t*)(sm + OFF_O1H + off) = packbf(h0, h1);
                *(uint32_t*)(sm + OFF_O1L + off) = packbf(l0, l1);
            }
    }
    __syncthreads();

    // ---- GEMM-B: out2 = p2 @ out1 ----  warp: m16 (wm2, 4) x n32 (wn2, 2)
    const int wm2 = wid & 3, wn2 = wid >> 2;
    float accB[4][4];
    #pragma unroll
    for (int nj = 0; nj < 4; nj++)
        #pragma unroll
        for (int v = 0; v < 4; v++) accB[nj][v] = 0.f;

    #pragma unroll
    for (int ks = 0; ks < 2; ks++) {
        uint32_t ah[4], al[4];
        {
            int ar = wm2 * 16 + (lane & 15);
            int ac = ks * 2 + (lane >> 4);
            uint32_t off = ar * 64 + (SWC(ar, ac) << 4);
            ldsm4(ah, sb + OFF_P2H + off);
            ldsm4(al, sb + OFF_P2L + off);
        }
        uint32_t bh[4][2], bl[4][2];
        #pragma unroll
        for (int bt = 0; bt < 2; bt++) {
            int grp = lane >> 3;
            int br = ks * 16 + ((grp & 1) << 3) + (lane & 7);
            int bc = wn2 * 4 + bt * 2 + (grp >> 1);
            uint32_t off = br * 128 + (SW8(br, bc) << 4);
            uint32_t tb[4];
            ldsm4t(tb, sb + OFF_O1H + off);
            bh[bt * 2][0] = tb[0]; bh[bt * 2][1] = tb[1];
            bh[bt * 2 + 1][0] = tb[2]; bh[bt * 2 + 1][1] = tb[3];
            ldsm4t(tb, sb + OFF_O1L + off);
            bl[bt * 2][0] = tb[0]; bl[bt * 2][1] = tb[1];
            bl[bt * 2 + 1][0] = tb[2]; bl[bt * 2 + 1][1] = tb[3];
        }
        #pragma unroll
        for (int nj = 0; nj < 4; nj++) {
            mma_bf16(accB[nj], ah, bh[nj]);
            mma_bf16(accB[nj], ah, bl[nj]);
            mma_bf16(accB[nj], al, bh[nj]);
        }
    }

    // gelu + LN2d over 64x64
    s = 0.f; q = 0.f;
    #pragma unroll
    for (int nj = 0; nj < 4; nj++)
        #pragma unroll
        for (int v = 0; v < 4; v++) {
            float g = gelu_exact(accB[nj][v]);
            accB[nj][v] = g; s += g; q += g * g;
        }
    blockReduce2(s, q);
    {
        float mean = s * (1.f / 4096.f);
        float var  = q * (1.f / 4096.f) - mean * mean;
        float rsig = rsqrtf(var + 1e-5f);
        // stage into P1H/P1L (linear [e][64d]); p1 no longer needed
        #pragma unroll
        for (int nj = 0; nj < 4; nj++)
            #pragma unroll
            for (int half = 0; half < 2; half++) {
                int e = wm2 * 16 + (lane >> 2) + half * 8;
                int d0 = wn2 * 32 + nj * 8 + ((lane & 3) << 1);
                float x0 = (accB[nj][half * 2 + 0] - mean) * rsig;
                float x1 = (accB[nj][half * 2 + 1] - mean) * rsig;
                __nv_bfloat16 h0 = __float2bfloat16(x0), h1 = __float2bfloat16(x1);
                __nv_bfloat16 l0 = __float2bfloat16(x0 - __bfloat162float(h0));
                __nv_bfloat16 l1 = __float2bfloat16(x1 - __bfloat162float(h1));
                uint32_t off = (e * 64 + d0) * 2;
                *(uint32_t*)(sm + OFF_P1H + off) = packbf(h0, h1);
                *(uint32_t*)(sm + OFF_P1L + off) = packbf(l0, l1);
            }
    }
    __syncthreads();

    // vectorized copy out
    {
        uint4* srcH = (uint4*)(sm + OFF_P1H);
        uint4* srcL = (uint4*)(sm + OFF_P1L);
        uint4* dstH = (uint4*)(g_out2_hi + (size_t)bq * OUTIN + h * 4096);
        uint4* dstL = (uint4*)(g_out2_lo + (size_t)bq * OUTIN + h * 4096);
        #pragma unroll
        for (int j = 0; j < 2; j++) {
            int i = t + j * 256;
            dstH[i] = srcH[i];
            dstL[i] = srcL[i];
        }
    }
}

// ---------------- split-K reduce + bias + final affine LN ----------------
__global__ void __launch_bounds__(256)
reduce_ln_kernel(const float* __restrict__ b_out,
                 const float* __restrict__ ln_w, const float* __restrict__ ln_b,
                 float* __restrict__ out)
{
    const int r = blockIdx.x;
    const int t = threadIdx.x;
    float x = b_out[t];
    #pragma unroll
    for (int z = 0; z < NSPLIT; z++)
        x += g_part[(size_t)z * BQ * QD + (size_t)r * QD + t];
    float s = x, q = x * x;
    blockReduce2(s, q);
    float mean = s * (1.f / 256.f);
    float var  = q * (1.f / 256.f) - mean * mean;
    float rsig = rsqrtf(var + 1e-5f);
    out[(size_t)r * QD + t] = (x - mean) * rsig * ln_w[t] + ln_b[t];
}

// ---------------- launch ----------------
extern "C" void kernel_launch(void* const* d_in, const int* in_sizes, int n_in,
                              void* d_out, int out_size)
{
    const float* qf = (const float*)d_in[0];
    const float* sf = (const float*)d_in[1];
    const float* Wg = (const float*)d_in[2];
    const float* bg = (const float*)d_in[3];
    const float* Wo = (const float*)d_in[4];
    const float* bo = (const float*)d_in[5];
    const float* lw = (const float*)d_in[6];
    const float* lb = (const float*)d_in[7];
    float* out = (float*)d_out;

    cudaFuncSetAttribute(hmma_gemm, cudaFuncAttributeMaxDynamicSharedMemorySize, SMEM_BYTES);

    float *params_p, *part_p;
    __nv_bfloat16 *qfh, *qfl, *wgh, *wgl, *woh, *wol, *o2h, *o2l;
    cudaGetSymbolAddress((void**)&params_p, g_params);
    cudaGetSymbolAddress((void**)&part_p, g_part);
    cudaGetSymbolAddress((void**)&qfh, g_qf_hi);
    cudaGetSymbolAddress((void**)&qfl, g_qf_lo);
    cudaGetSymbolAddress((void**)&wgh, g_wgt_hi);
    cudaGetSymbolAddress((void**)&wgl, g_wgt_lo);
    cudaGetSymbolAddress((void**)&woh, g_wot_hi);
    cudaGetSymbolAddress((void**)&wol, g_wot_lo);
    cudaGetSymbolAddress((void**)&o2h, g_out2_hi);
    cudaGetSymbolAddress((void**)&o2l, g_out2_lo);

    // prep
    split_kernel<<<(BQ * QD + 255) / 256, 256>>>(qf, qfh, qfl, BQ * QD);
    transpose_split_kernel<<<dim3(TOT / 32, QD / 32), 256>>>(Wg, wgh, wgl, QD, TOT);
    transpose_split_kernel<<<dim3(QD / 32, OUTIN / 32), 256>>>(Wo, woh, wol, OUTIN, QD);

    // GEMM1: params = qf @ W_gen + b_gen   (3600 x 24576 x 256)
    hmma_gemm<<<dim3(TOT / 128, (BQ + 127) / 128, 1), 256, SMEM_BYTES>>>(
        qfh, qfl, wgh, wgl, bg, params_p, BQ, QD, QD / 32, TOT, 0);

    // fused mixers (HMMA)
    mixer_hmma<<<dim3(BQ, 4), 256>>>(sf);

    // GEMM3 split-K=16: out2 @ W_out partials   (3600 x 256 x 16384)
    hmma_gemm<<<dim3(QD / 128, (BQ + 127) / 128, NSPLIT), 256, SMEM_BYTES>>>(
        o2h, o2l, woh, wol, nullptr, part_p, BQ, OUTIN,
        (OUTIN / NSPLIT) / 32, QD, (size_t)BQ * QD);

    // reduce + final LN
    reduce_ln_kernel<<<BQ, 256>>>(bo, lw, lb, out);
}